// round 7
// baseline (speedup 1.0000x reference)
#include <cuda_runtime.h>
#include <cuda_bf16.h>

#define NNODES 1000000
#define D 128
#define G 25000
#define STEPS 8

// Persistent state (allocation-free scratch)
__device__ __align__(16) float g_carry[(size_t)G * D];
__device__ __align__(16) float g_memory[(size_t)G * D];
__device__ __align__(16) float g_readout[(size_t)G * D];
__device__ int g_segoff[G + 1];
// Split-bf16 weights, transposed to [n][k] (k contiguous) for fragment loads
__device__ __align__(16) __nv_bfloat16 g_Whi[512 * 256];
__device__ __align__(16) __nv_bfloat16 g_Wlo[512 * 256];

__device__ __forceinline__ float fast_tanh(float x) {
    float y;
    asm("tanh.approx.f32 %0, %1;" : "=f"(y) : "f"(x));
    return y;
}
__device__ __forceinline__ float fast_sigmoid(float x) {
    return 0.5f * fast_tanh(0.5f * x) + 0.5f;
}

// ---------------------------------------------------------------------------
// Segment offsets: lower_bound(g) over sorted graph_indicator
// ---------------------------------------------------------------------------
__global__ void segoff_kernel(const int* __restrict__ gi, int n) {
    int g = blockIdx.x * blockDim.x + threadIdx.x;
    if (g > G) return;
    int lo = 0, hi = n;
    while (lo < hi) {
        int mid = (lo + hi) >> 1;
        if (gi[mid] < g) lo = mid + 1; else hi = mid;
    }
    g_segoff[g] = lo;
}

__global__ void zero_state_kernel() {
    int i = blockIdx.x * blockDim.x + threadIdx.x;
    if (i < G * D) { g_carry[i] = 0.f; g_memory[i] = 0.f; }
}

// ---------------------------------------------------------------------------
// W [k=256][n=512] fp32 -> transposed split-bf16 Whi/Wlo [n=512][k=256]
// ---------------------------------------------------------------------------
__global__ void wsplit_kernel(const float* __restrict__ W) {
    int idx = blockIdx.x * blockDim.x + threadIdx.x;
    if (idx >= 256 * 512) return;
    int k = idx >> 9;          // 0..255
    int n = idx & 511;         // 0..511
    float v = W[idx];
    __nv_bfloat16 hi = __float2bfloat16(v);
    __nv_bfloat16 lo = __float2bfloat16(v - __bfloat162float(hi));
    g_Whi[n * 256 + k] = hi;
    g_Wlo[n * 256 + k] = lo;
}

// ---------------------------------------------------------------------------
// Fused attention readout: one warp per graph, single pass, online softmax,
// 2-deep load pipeline for MLP=2. Lane l owns dims [4l, 4l+4).
// ---------------------------------------------------------------------------
__global__ void readout_kernel(const float* __restrict__ nf, float* __restrict__ out) {
    int warp = (blockIdx.x * blockDim.x + threadIdx.x) >> 5;
    if (warp >= G) return;
    int lane = threadIdx.x & 31;
    int g = warp;
    int s = g_segoff[g], e = g_segoff[g + 1];

    float4 c4 = *((const float4*)(g_carry + (size_t)g * D) + lane);

    float m = -3.4e38f, den = 0.f;
    float ax = 0.f, ay = 0.f, az = 0.f, aw = 0.f;

    const float4* nf4 = (const float4*)nf;
    if (s < e) {
        float4 f4 = __ldg(nf4 + (size_t)s * (D / 4) + lane);
        for (int i = s; i < e; ++i) {
            float4 nxt;
            if (i + 1 < e) nxt = __ldg(nf4 + (size_t)(i + 1) * (D / 4) + lane);
            float p = f4.x * c4.x + f4.y * c4.y + f4.z * c4.z + f4.w * c4.w;
            #pragma unroll
            for (int o = 16; o; o >>= 1) p += __shfl_xor_sync(0xffffffffu, p, o);
            if (p > m) {
                float sc = __expf(m - p);   // first iter: underflows to 0
                den *= sc; ax *= sc; ay *= sc; az *= sc; aw *= sc;
                m = p;
            }
            float w = __expf(p - m);
            den += w;
            ax += w * f4.x; ay += w * f4.y; az += w * f4.z; aw += w * f4.w;
            f4 = nxt;
        }
    }

    float inv = (den > 0.f) ? 1.f / den : 0.f;   // empty graph -> readout 0
    float4 r = make_float4(ax * inv, ay * inv, az * inv, aw * inv);
    *((float4*)(g_readout + (size_t)g * D) + lane) = r;

    if (out) {
        *((float4*)(out + (size_t)g * 2 * D) + lane)     = c4;  // carry half
        *((float4*)(out + (size_t)g * 2 * D + D) + lane) = r;   // readout half
    }
}

// ---------------------------------------------------------------------------
// Tensor-core LSTM step. z = [carry, readout] @ W + bias via split-bf16
// (3 MMAs per tile: hi*hi + hi*lo + lo*hi ~ fp32 accuracy), gates in regs.
//
// Block: 256 threads = 8 warps, M=32 graphs, full N=512.
// Warp w owns d-range [16w, 16w+16) for ALL FOUR gates, so u/f/c/o for a
// given (g,d) land in the same thread -> pure register epilogue, no z smem.
// ---------------------------------------------------------------------------
__device__ __forceinline__ void mma16816(float* c, const unsigned* a, unsigned b0, unsigned b1) {
    asm volatile(
        "mma.sync.aligned.m16n8k16.row.col.f32.bf16.bf16.f32 "
        "{%0,%1,%2,%3}, {%4,%5,%6,%7}, {%8,%9}, {%0,%1,%2,%3};"
        : "+f"(c[0]), "+f"(c[1]), "+f"(c[2]), "+f"(c[3])
        : "r"(a[0]), "r"(a[1]), "r"(a[2]), "r"(a[3]), "r"(b0), "r"(b1));
}

#define XPAD 264   // 256 + 8 bf16 pad -> 528B row stride, conflict-free frags

__global__ __launch_bounds__(256) void lstm_kernel(const float* __restrict__ bias) {
    __shared__ __nv_bfloat16 xs_hi[32][XPAD];
    __shared__ __nv_bfloat16 xs_lo[32][XPAD];

    int tid = threadIdx.x;
    int g0 = blockIdx.x * 32;
    int w = tid >> 5;              // warp 0..7
    int lane = tid & 31;
    int gid = lane >> 2;           // groupID 0..7
    int tig = lane & 3;            // threadID_in_group 0..3

    // --- stage x = [carry | readout] into smem as hi/lo bf16 (float4 loads) ---
    for (int idx = tid; idx < 32 * 64; idx += 256) {
        int r  = idx >> 6;          // row within tile (0..31)
        int kq = idx & 63;          // float4 index (0..63) -> k = 4*kq
        int g = g0 + r;
        float4 v = make_float4(0.f, 0.f, 0.f, 0.f);
        if (g < G) {
            if (kq < 32) v = *((const float4*)(g_carry   + (size_t)g * D) + kq);
            else         v = *((const float4*)(g_readout + (size_t)g * D) + (kq - 32));
        }
        int k = kq * 4;
        float vv[4] = {v.x, v.y, v.z, v.w};
        #pragma unroll
        for (int j = 0; j < 4; j++) {
            __nv_bfloat16 hi = __float2bfloat16(vv[j]);
            xs_hi[r][k + j] = hi;
            xs_lo[r][k + j] = __float2bfloat16(vv[j] - __bfloat162float(hi));
        }
    }
    __syncthreads();

    // acc[mtile][h][gate][ci]
    float acc[2][2][4][4];
    #pragma unroll
    for (int mt = 0; mt < 2; mt++)
        #pragma unroll
        for (int h = 0; h < 2; h++)
            #pragma unroll
            for (int gt = 0; gt < 4; gt++)
                #pragma unroll
                for (int ci = 0; ci < 4; ci++) acc[mt][h][gt][ci] = 0.f;

    #pragma unroll 4
    for (int kt = 0; kt < 16; ++kt) {
        int kc = kt * 16 + 2 * tig;

        unsigned ah[2][4], al[2][4];
        #pragma unroll
        for (int mt = 0; mt < 2; mt++) {
            int r = mt * 16 + gid;
            ah[mt][0] = *(const unsigned*)&xs_hi[r][kc];
            ah[mt][1] = *(const unsigned*)&xs_hi[r + 8][kc];
            ah[mt][2] = *(const unsigned*)&xs_hi[r][kc + 8];
            ah[mt][3] = *(const unsigned*)&xs_hi[r + 8][kc + 8];
            al[mt][0] = *(const unsigned*)&xs_lo[r][kc];
            al[mt][1] = *(const unsigned*)&xs_lo[r + 8][kc];
            al[mt][2] = *(const unsigned*)&xs_lo[r][kc + 8];
            al[mt][3] = *(const unsigned*)&xs_lo[r + 8][kc + 8];
        }

        #pragma unroll
        for (int gt = 0; gt < 4; gt++) {
            #pragma unroll
            for (int h = 0; h < 2; h++) {
                int n = gt * 128 + w * 16 + h * 8 + gid;
                const __nv_bfloat16* bh = g_Whi + (size_t)n * 256 + kc;
                const __nv_bfloat16* bl = g_Wlo + (size_t)n * 256 + kc;
                unsigned bh0 = *(const unsigned*)bh;
                unsigned bh1 = *(const unsigned*)(bh + 8);
                unsigned bl0 = *(const unsigned*)bl;
                unsigned bl1 = *(const unsigned*)(bl + 8);
                #pragma unroll
                for (int mt = 0; mt < 2; mt++) {
                    mma16816(acc[mt][h][gt], ah[mt], bh0, bh1);   // hi*hi
                    mma16816(acc[mt][h][gt], ah[mt], bl0, bl1);   // hi*lo
                    mma16816(acc[mt][h][gt], al[mt], bh0, bh1);   // lo*hi
                }
            }
        }
    }

    // --- register epilogue: gates + LSTM state update ---
    #pragma unroll
    for (int h = 0; h < 2; h++) {
        #pragma unroll
        for (int cs = 0; cs < 2; cs++) {
            int d = w * 16 + h * 8 + 2 * tig + cs;
            float bu = __ldg(bias + d);
            float bf = __ldg(bias + 128 + d);
            float bc = __ldg(bias + 256 + d);
            float bo = __ldg(bias + 384 + d);
            #pragma unroll
            for (int mt = 0; mt < 2; mt++) {
                #pragma unroll
                for (int rs = 0; rs < 2; rs++) {
                    int g = g0 + mt * 16 + rs * 8 + gid;
                    if (g >= G) continue;
                    int ci = rs * 2 + cs;
                    float su = fast_sigmoid(acc[mt][h][0][ci] + bu);
                    float sf = fast_sigmoid(acc[mt][h][1][ci] + bf);
                    float tc = fast_tanh   (acc[mt][h][2][ci] + bc);
                    float so = fast_sigmoid(acc[mt][h][3][ci] + bo);
                    size_t idx = (size_t)g * D + d;
                    float mem = sf * g_memory[idx] + su * tc;
                    g_memory[idx] = mem;
                    g_carry[idx] = so * fast_tanh(mem);
                }
            }
        }
    }
}

// ---------------------------------------------------------------------------
extern "C" void kernel_launch(void* const* d_in, const int* in_sizes, int n_in,
                              void* d_out, int out_size) {
    const float* nf   = (const float*)d_in[0];
    const int*   gi   = (const int*)d_in[1];
    const float* W    = (const float*)d_in[2];
    const float* bias = (const float*)d_in[3];
    float* out = (float*)d_out;
    int n = in_sizes[1];   // number of nodes (graph_indicator length)

    segoff_kernel<<<(G + 1 + 255) / 256, 256>>>(gi, n);
    zero_state_kernel<<<(G * D + 255) / 256, 256>>>();
    wsplit_kernel<<<(256 * 512 + 255) / 256, 256>>>(W);

    for (int s = 0; s < STEPS; ++s) {
        readout_kernel<<<(G + 7) / 8, 256>>>(nf, (s == STEPS - 1) ? out : nullptr);
        // The reference's final LSTM update never affects the output -> skip it.
        if (s < STEPS - 1) lstm_kernel<<<(G + 31) / 32, 256>>>(bias);
    }
}

// round 8
// speedup vs baseline: 1.2071x; 1.2071x over previous
#include <cuda_runtime.h>
#include <cuda_bf16.h>
#include <cstdint>

#define D 128
#define G 25000
#define STEPS 8

#define MT 64                 // graphs per LSTM block
#define LSTM_THREADS 512
#define XPAD 264              // A smem row: 256 + 8 bf16 pad -> 528B, conflict-free
#define BROW 12               // B smem row: 8 data words + 4 pad words = 48B, conflict-free
#define A_LO_OFF (MT * XPAD * 2)
#define B_OFF    (2 * MT * XPAD * 2)          // 67584
#define B_ARR_SZ (512 * BROW * 4)             // 24576 (one of hi/lo)
#define B_BUF_SZ (2 * B_ARR_SZ)               // 49152 (hi+lo, one k-slice)
#define LSTM_SMEM (B_OFF + 2 * B_BUF_SZ)      // 165888

// Persistent state (allocation-free scratch)
__device__ __align__(16) float g_carry[(size_t)G * D];
__device__ __align__(16) float g_memory[(size_t)G * D];
__device__ __align__(16) float g_readout[(size_t)G * D];
__device__ int g_segoff[G + 1];
// Split-bf16 weights, transposed to [n][k] (k contiguous)
__device__ __align__(16) __nv_bfloat16 g_Whi[512 * 256];
__device__ __align__(16) __nv_bfloat16 g_Wlo[512 * 256];

__device__ __forceinline__ float fast_tanh(float x) {
    float y;
    asm("tanh.approx.f32 %0, %1;" : "=f"(y) : "f"(x));
    return y;
}
__device__ __forceinline__ float fast_sigmoid(float x) {
    return 0.5f * fast_tanh(0.5f * x) + 0.5f;
}
__device__ __forceinline__ void cp_async16(uint32_t dst, const void* src) {
    asm volatile("cp.async.cg.shared.global [%0], [%1], 16;" :: "r"(dst), "l"(src));
}

// ---------------------------------------------------------------------------
// Segment offsets: lower_bound(g) over sorted graph_indicator
// ---------------------------------------------------------------------------
__global__ void segoff_kernel(const int* __restrict__ gi, int n) {
    int g = blockIdx.x * blockDim.x + threadIdx.x;
    if (g > G) return;
    int lo = 0, hi = n;
    while (lo < hi) {
        int mid = (lo + hi) >> 1;
        if (gi[mid] < g) lo = mid + 1; else hi = mid;
    }
    g_segoff[g] = lo;
}

__global__ void zero_state_kernel() {
    int i = blockIdx.x * blockDim.x + threadIdx.x;
    if (i < G * D) { g_carry[i] = 0.f; g_memory[i] = 0.f; }
}

// W [k=256][n=512] fp32 -> transposed split-bf16 Whi/Wlo [n=512][k=256]
__global__ void wsplit_kernel(const float* __restrict__ W) {
    int idx = blockIdx.x * blockDim.x + threadIdx.x;
    if (idx >= 256 * 512) return;
    int k = idx >> 9;
    int n = idx & 511;
    float v = W[idx];
    __nv_bfloat16 hi = __float2bfloat16(v);
    __nv_bfloat16 lo = __float2bfloat16(v - __bfloat162float(hi));
    g_Whi[n * 256 + k] = hi;
    g_Wlo[n * 256 + k] = lo;
}

// ---------------------------------------------------------------------------
// Fused attention readout: one warp per graph, single pass, online softmax,
// 2-node pairwise processing (two independent shuffle chains -> 2x ILP).
// Lane l owns dims [4l, 4l+4).
// ---------------------------------------------------------------------------
__global__ void readout_kernel(const float* __restrict__ nf, float* __restrict__ out) {
    int warp = (blockIdx.x * blockDim.x + threadIdx.x) >> 5;
    if (warp >= G) return;
    int lane = threadIdx.x & 31;
    int g = warp;
    int s = g_segoff[g], e = g_segoff[g + 1];

    float4 c4 = *((const float4*)(g_carry + (size_t)g * D) + lane);

    float m = -3.4e38f, den = 0.f;
    float ax = 0.f, ay = 0.f, az = 0.f, aw = 0.f;

    const float4* nf4 = (const float4*)nf;
    int i = s;
    for (; i + 1 < e; i += 2) {
        float4 fa = __ldg(nf4 + (size_t)i * (D / 4) + lane);
        float4 fb = __ldg(nf4 + (size_t)(i + 1) * (D / 4) + lane);
        float pa = fa.x * c4.x + fa.y * c4.y + fa.z * c4.z + fa.w * c4.w;
        float pb = fb.x * c4.x + fb.y * c4.y + fb.z * c4.z + fb.w * c4.w;
        #pragma unroll
        for (int o = 16; o; o >>= 1) {
            pa += __shfl_xor_sync(0xffffffffu, pa, o);
            pb += __shfl_xor_sync(0xffffffffu, pb, o);
        }
        float mn = fmaxf(m, fmaxf(pa, pb));
        float sc = __expf(m - mn);          // first iter: exp(-inf) -> 0
        float wa = __expf(pa - mn);
        float wb = __expf(pb - mn);
        den = den * sc + wa + wb;
        ax = ax * sc + wa * fa.x + wb * fb.x;
        ay = ay * sc + wa * fa.y + wb * fb.y;
        az = az * sc + wa * fa.z + wb * fb.z;
        aw = aw * sc + wa * fa.w + wb * fb.w;
        m = mn;
    }
    if (i < e) {
        float4 fa = __ldg(nf4 + (size_t)i * (D / 4) + lane);
        float pa = fa.x * c4.x + fa.y * c4.y + fa.z * c4.z + fa.w * c4.w;
        #pragma unroll
        for (int o = 16; o; o >>= 1) pa += __shfl_xor_sync(0xffffffffu, pa, o);
        float mn = fmaxf(m, pa);
        float sc = __expf(m - mn);
        float wa = __expf(pa - mn);
        den = den * sc + wa;
        ax = ax * sc + wa * fa.x;
        ay = ay * sc + wa * fa.y;
        az = az * sc + wa * fa.z;
        aw = aw * sc + wa * fa.w;
    }

    float inv = (den > 0.f) ? 1.f / den : 0.f;   // empty graph -> readout 0
    float4 r = make_float4(ax * inv, ay * inv, az * inv, aw * inv);
    *((float4*)(g_readout + (size_t)g * D) + lane) = r;

    if (out) {
        *((float4*)(out + (size_t)g * 2 * D) + lane)     = c4;
        *((float4*)(out + (size_t)g * 2 * D + D) + lane) = r;
    }
}

// ---------------------------------------------------------------------------
// Tensor-core LSTM step. z = [carry, readout] @ W + bias via split-bf16
// (3 MMAs: hi*hi + hi*lo + lo*hi ~ fp32 accuracy), gates in registers.
//
// Block: 512 threads = 16 warps, M=64 graphs, full N=512. W is streamed
// global->smem in 16-k slices, double-buffered with cp.async so MMAs never
// wait on L2. Warp (wr,wc): wr = m-row (32 graphs), wc owns d-range
// [16wc,16wc+16) for ALL FOUR gates -> u/f/c/o of a given (g,d) land in the
// same thread -> pure register epilogue.
// ---------------------------------------------------------------------------
__device__ __forceinline__ void mma16816(float* c, const unsigned* a, unsigned b0, unsigned b1) {
    asm volatile(
        "mma.sync.aligned.m16n8k16.row.col.f32.bf16.bf16.f32 "
        "{%0,%1,%2,%3}, {%4,%5,%6,%7}, {%8,%9}, {%0,%1,%2,%3};"
        : "+f"(c[0]), "+f"(c[1]), "+f"(c[2]), "+f"(c[3])
        : "r"(a[0]), "r"(a[1]), "r"(a[2]), "r"(a[3]), "r"(b0), "r"(b1));
}

__global__ __launch_bounds__(LSTM_THREADS, 1) void lstm_kernel(const float* __restrict__ bias) {
    extern __shared__ char sm[];
    __nv_bfloat16* xs_hi = (__nv_bfloat16*)sm;
    __nv_bfloat16* xs_lo = (__nv_bfloat16*)(sm + A_LO_OFF);
    uint32_t sm_base = (uint32_t)__cvta_generic_to_shared(sm);

    int tid = threadIdx.x;
    int g0 = blockIdx.x * MT;
    int w = tid >> 5, lane = tid & 31;
    int gid = lane >> 2, tig = lane & 3;
    int wr = w >> 3, wc = w & 7;

    // --- stage x = [carry | readout] as hi/lo bf16 (float4 loads) ---
    for (int idx = tid; idx < MT * 64; idx += LSTM_THREADS) {
        int r  = idx >> 6;
        int kq = idx & 63;
        int g = g0 + r;
        float4 v = make_float4(0.f, 0.f, 0.f, 0.f);
        if (g < G) {
            if (kq < 32) v = *((const float4*)(g_carry   + (size_t)g * D) + kq);
            else         v = *((const float4*)(g_readout + (size_t)g * D) + (kq - 32));
        }
        int k = kq * 4;
        float vv[4] = {v.x, v.y, v.z, v.w};
        #pragma unroll
        for (int j = 0; j < 4; j++) {
            __nv_bfloat16 hi = __float2bfloat16(vv[j]);
            xs_hi[r * XPAD + k + j] = hi;
            xs_lo[r * XPAD + k + j] = __float2bfloat16(vv[j] - __bfloat162float(hi));
        }
    }

    // --- B slice loader: 2048 x 16B chunks (hi+lo, all 512 n, 16 k) ---
    auto load_B = [&](int kt, int buf) {
        #pragma unroll
        for (int j = 0; j < 4; j++) {
            int c = tid + j * LSTM_THREADS;        // 0..2047
            int half = c & 1;
            int n = (c >> 1) & 511;
            int arr = c >> 10;                      // 0=hi 1=lo
            const __nv_bfloat16* src =
                (arr ? g_Wlo : g_Whi) + (size_t)n * 256 + kt * 16 + half * 8;
            uint32_t dst = sm_base + B_OFF + buf * B_BUF_SZ + arr * B_ARR_SZ
                         + n * (BROW * 4) + half * 16;
            cp_async16(dst, src);
        }
        asm volatile("cp.async.commit_group;");
    };

    load_B(0, 0);

    float acc[2][2][4][4];
    #pragma unroll
    for (int mt = 0; mt < 2; mt++)
        #pragma unroll
        for (int h = 0; h < 2; h++)
            #pragma unroll
            for (int gt = 0; gt < 4; gt++)
                #pragma unroll
                for (int ci = 0; ci < 4; ci++) acc[mt][h][gt][ci] = 0.f;

    for (int kt = 0; kt < 16; ++kt) {
        int buf = kt & 1;
        if (kt < 15) {
            load_B(kt + 1, buf ^ 1);
            asm volatile("cp.async.wait_group 1;");
        } else {
            asm volatile("cp.async.wait_group 0;");
        }
        __syncthreads();

        int kc = kt * 16 + 2 * tig;
        unsigned ah[2][4], al[2][4];
        #pragma unroll
        for (int mt = 0; mt < 2; mt++) {
            int r = wr * 32 + mt * 16 + gid;
            const __nv_bfloat16* ph = xs_hi + r * XPAD;
            const __nv_bfloat16* pl = xs_lo + r * XPAD;
            ah[mt][0] = *(const unsigned*)(ph + kc);
            ah[mt][1] = *(const unsigned*)(ph + 8 * XPAD + kc);
            ah[mt][2] = *(const unsigned*)(ph + kc + 8);
            ah[mt][3] = *(const unsigned*)(ph + 8 * XPAD + kc + 8);
            al[mt][0] = *(const unsigned*)(pl + kc);
            al[mt][1] = *(const unsigned*)(pl + 8 * XPAD + kc);
            al[mt][2] = *(const unsigned*)(pl + kc + 8);
            al[mt][3] = *(const unsigned*)(pl + 8 * XPAD + kc + 8);
        }

        const uint32_t* Bh = (const uint32_t*)(sm + B_OFF + buf * B_BUF_SZ);
        const uint32_t* Bl = (const uint32_t*)(sm + B_OFF + buf * B_BUF_SZ + B_ARR_SZ);

        #pragma unroll
        for (int gt = 0; gt < 4; gt++) {
            #pragma unroll
            for (int h = 0; h < 2; h++) {
                int n = gt * 128 + wc * 16 + h * 8 + gid;
                unsigned bh0 = Bh[n * BROW + tig];
                unsigned bh1 = Bh[n * BROW + tig + 4];
                unsigned bl0 = Bl[n * BROW + tig];
                unsigned bl1 = Bl[n * BROW + tig + 4];
                #pragma unroll
                for (int mt = 0; mt < 2; mt++) {
                    mma16816(acc[mt][h][gt], ah[mt], bh0, bh1);   // hi*hi
                    mma16816(acc[mt][h][gt], ah[mt], bl0, bl1);   // hi*lo
                    mma16816(acc[mt][h][gt], al[mt], bh0, bh1);   // lo*hi
                }
            }
        }
        __syncthreads();   // protect buf before it is reloaded at kt+2
    }

    // --- register epilogue: gates + LSTM state update ---
    #pragma unroll
    for (int h = 0; h < 2; h++) {
        #pragma unroll
        for (int cs = 0; cs < 2; cs++) {
            int d = wc * 16 + h * 8 + 2 * tig + cs;
            float bu = __ldg(bias + d);
            float bf = __ldg(bias + 128 + d);
            float bc = __ldg(bias + 256 + d);
            float bo = __ldg(bias + 384 + d);
            #pragma unroll
            for (int mt = 0; mt < 2; mt++) {
                #pragma unroll
                for (int rs = 0; rs < 2; rs++) {
                    int g = g0 + wr * 32 + mt * 16 + rs * 8 + gid;
                    if (g >= G) continue;
                    int ci = rs * 2 + cs;
                    float su = fast_sigmoid(acc[mt][h][0][ci] + bu);
                    float sf = fast_sigmoid(acc[mt][h][1][ci] + bf);
                    float tc = fast_tanh   (acc[mt][h][2][ci] + bc);
                    float so = fast_sigmoid(acc[mt][h][3][ci] + bo);
                    size_t idx = (size_t)g * D + d;
                    float mem = sf * g_memory[idx] + su * tc;
                    g_memory[idx] = mem;
                    g_carry[idx] = so * fast_tanh(mem);
                }
            }
        }
    }
}

// ---------------------------------------------------------------------------
extern "C" void kernel_launch(void* const* d_in, const int* in_sizes, int n_in,
                              void* d_out, int out_size) {
    const float* nf   = (const float*)d_in[0];
    const int*   gi   = (const int*)d_in[1];
    const float* W    = (const float*)d_in[2];
    const float* bias = (const float*)d_in[3];
    float* out = (float*)d_out;
    int n = in_sizes[1];

    static int smem_set = 0;
    if (!smem_set) {
        cudaFuncSetAttribute(lstm_kernel,
                             cudaFuncAttributeMaxDynamicSharedMemorySize, LSTM_SMEM);
        smem_set = 1;
    }

    segoff_kernel<<<(G + 1 + 255) / 256, 256>>>(gi, n);
    zero_state_kernel<<<(G * D + 255) / 256, 256>>>();
    wsplit_kernel<<<(256 * 512 + 255) / 256, 256>>>(W);

    for (int s = 0; s < STEPS; ++s) {
        readout_kernel<<<(G + 7) / 8, 256>>>(nf, (s == STEPS - 1) ? out : nullptr);
        // The reference's final LSTM update never affects the output -> skip it.
        if (s < STEPS - 1)
            lstm_kernel<<<(G + MT - 1) / MT, LSTM_THREADS, LSTM_SMEM>>>(bias);
    }
}